// round 1
// baseline (speedup 1.0000x reference)
#include <cuda_runtime.h>

#define BATCH 2048
#define NPTS  4095
#define TPB   1024
#define EPT   4      // TPB*EPT = 4096 >= NPTS

__device__ float g_partial[BATCH];

__global__ __launch_bounds__(TPB)
void mpd_batch_kernel(const float* __restrict__ o3,
                      const float* __restrict__ s3,
                      const float* __restrict__ o2,
                      const float* __restrict__ s2,
                      const float* __restrict__ df)
{
    const int b = blockIdx.x;
    const int t = threadIdx.x;
    const unsigned lane = t & 31u;
    const unsigned warp = t >> 5;

    const float* __restrict__ r3p  = s3 + (size_t)(b * 3 + 0) * NPTS;
    const float* __restrict__ th3p = s3 + (size_t)(b * 3 + 1) * NPTS;
    const float* __restrict__ ph3p = s3 + (size_t)(b * 3 + 2) * NPTS;
    const float* __restrict__ r2p  = s2 + (size_t)(b * 3 + 0) * NPTS;
    const float* __restrict__ th2p = s2 + (size_t)(b * 3 + 1) * NPTS;
    const float* __restrict__ ph2p = s2 + (size_t)(b * 3 + 2) * NPTS;
    const float* __restrict__ dthp = df + (size_t)(b * 2 + 0) * NPTS;
    const float* __restrict__ dphp = df + (size_t)(b * 2 + 1) * NPTS;

    const float dx = o3[b * 3 + 0] - o2[b * 3 + 0];
    const float dy = o3[b * 3 + 1] - o2[b * 3 + 1];
    const float dz = o3[b * 3 + 2] - o2[b * 3 + 2];

    // ---- per-thread: compute s_i = shape3D_i - shape2D_i for 4 consecutive i
    float sx[EPT], sy[EPT], sz[EPT];
    const int base = t * EPT;
    #pragma unroll
    for (int k = 0; k < EPT; k++) {
        const int i = base + k;
        float vx = 0.f, vy = 0.f, vz = 0.f;
        if (i < NPTS) {
            float r3  = r3p[i];
            float th3 = th3p[i] + dthp[i];
            float ph3 = ph3p[i] + dphp[i];
            float st, ct, sp, cp;
            __sincosf(th3, &st, &ct);
            __sincosf(ph3, &sp, &cp);
            float rst = r3 * st;
            vx = rst * cp; vy = rst * sp; vz = r3 * ct;

            float r2  = r2p[i];
            float th2 = th2p[i];
            float ph2 = ph2p[i];
            __sincosf(th2, &st, &ct);
            __sincosf(ph2, &sp, &cp);
            rst = r2 * st;
            vx -= rst * cp; vy -= rst * sp; vz -= r2 * ct;
        }
        sx[k] = vx; sy[k] = vy; sz[k] = vz;
    }

    // ---- thread-local inclusive scan
    #pragma unroll
    for (int k = 1; k < EPT; k++) {
        sx[k] += sx[k - 1];
        sy[k] += sy[k - 1];
        sz[k] += sz[k - 1];
    }
    const float tx = sx[EPT - 1], ty = sy[EPT - 1], tz = sz[EPT - 1];

    // ---- warp inclusive scan of thread totals
    float ix = tx, iy = ty, iz = tz;
    #pragma unroll
    for (int o = 1; o < 32; o <<= 1) {
        float ax = __shfl_up_sync(0xFFFFFFFFu, ix, o);
        float ay = __shfl_up_sync(0xFFFFFFFFu, iy, o);
        float az = __shfl_up_sync(0xFFFFFFFFu, iz, o);
        if (lane >= (unsigned)o) { ix += ax; iy += ay; iz += az; }
    }

    // ---- cross-warp scan via shared memory (32 warps)
    __shared__ float wsx[32], wsy[32], wsz[32];
    __shared__ float red[32];
    if (lane == 31) { wsx[warp] = ix; wsy[warp] = iy; wsz[warp] = iz; }
    __syncthreads();
    if (warp == 0) {
        float vx = wsx[lane], vy = wsy[lane], vz = wsz[lane];
        #pragma unroll
        for (int o = 1; o < 32; o <<= 1) {
            float ax = __shfl_up_sync(0xFFFFFFFFu, vx, o);
            float ay = __shfl_up_sync(0xFFFFFFFFu, vy, o);
            float az = __shfl_up_sync(0xFFFFFFFFu, vz, o);
            if (lane >= (unsigned)o) { vx += ax; vy += ay; vz += az; }
        }
        wsx[lane] = vx; wsy[lane] = vy; wsz[lane] = vz;
    }
    __syncthreads();

    // exclusive offset for this thread = d + (warps before) + (lanes before)
    float offx = dx + (ix - tx);
    float offy = dy + (iy - ty);
    float offz = dz + (iz - tz);
    if (warp > 0) {
        offx += wsx[warp - 1];
        offy += wsy[warp - 1];
        offz += wsz[warp - 1];
    }

    // ---- abs-sum over positions owned by this thread
    float acc = 0.f;
    if (t == 0) acc = fabsf(dx) + fabsf(dy) + fabsf(dz);  // position j=0 (origin)
    #pragma unroll
    for (int k = 0; k < EPT; k++) {
        if (base + k < NPTS) {
            acc += fabsf(offx + sx[k]) + fabsf(offy + sy[k]) + fabsf(offz + sz[k]);
        }
    }

    // ---- block reduce
    #pragma unroll
    for (int o = 16; o > 0; o >>= 1)
        acc += __shfl_down_sync(0xFFFFFFFFu, acc, o);
    if (lane == 0) red[warp] = acc;
    __syncthreads();
    if (warp == 0) {
        float a = red[lane];
        #pragma unroll
        for (int o = 16; o > 0; o >>= 1)
            a += __shfl_down_sync(0xFFFFFFFFu, a, o);
        if (lane == 0) g_partial[b] = a * (1.0f / (NPTS + 1));
    }
}

__global__ __launch_bounds__(1024)
void mpd_reduce_kernel(float* __restrict__ out)
{
    __shared__ float red[32];
    const int t = threadIdx.x;
    const unsigned lane = t & 31u;
    const unsigned warp = t >> 5;
    float a = g_partial[t] + g_partial[t + 1024];
    #pragma unroll
    for (int o = 16; o > 0; o >>= 1)
        a += __shfl_down_sync(0xFFFFFFFFu, a, o);
    if (lane == 0) red[warp] = a;
    __syncthreads();
    if (warp == 0) {
        float v = red[lane];
        #pragma unroll
        for (int o = 16; o > 0; o >>= 1)
            v += __shfl_down_sync(0xFFFFFFFFu, v, o);
        if (lane == 0) out[0] = v;
    }
}

extern "C" void kernel_launch(void* const* d_in, const int* in_sizes, int n_in,
                              void* d_out, int out_size)
{
    const float* o3 = (const float*)d_in[0];  // origin_3D        (B,3,1)
    const float* s3 = (const float*)d_in[1];  // spherical_3D     (B,3,N)
    const float* o2 = (const float*)d_in[2];  // origin_2D        (B,3,1)
    const float* s2 = (const float*)d_in[3];  // spherical_2D     (B,3,N)
    const float* df = (const float*)d_in[4];  // deformation_field(B,2,N)
    float* out = (float*)d_out;

    mpd_batch_kernel<<<BATCH, TPB>>>(o3, s3, o2, s2, df);
    mpd_reduce_kernel<<<1, 1024>>>(out);
}